// round 15
// baseline (speedup 1.0000x reference)
#include <cuda_runtime.h>
#include <cuda_bf16.h>
#include <math.h>
#include <stdint.h>

#define SZ 4096
#define NW (SZ*SZ)

// ---------------- scratch (static __device__, no runtime alloc) -------------
__device__ __align__(16) float         g_w1t[NW];  // tf32-rounded w_mu^T [N][K]
__device__ __align__(16) __nv_bfloat16 g_a2h[NW];  // bf16(mu^2)        [B][K]
__device__ __align__(16) __nv_bfloat16 g_w2h[NW];  // bf16(sp(w_sig))^T [N][K]
#define PREP_W_BLOCKS 16384
__device__ float g_part0[PREP_W_BLOCKS];   // sum log(sp)
__device__ float g_part1[PREP_W_BLOCKS];   // sum sp
__device__ float g_part2[PREP_W_BLOCKS];   // sum |w_mu|

__device__ __forceinline__ float softplus_fast(float x) {
    return log1pf(__expf(x));   // args <= -2.2: no overflow
}
__device__ __forceinline__ float softplusf(float x) {
    return x > 20.0f ? x : log1pf(expf(x));
}
__device__ __forceinline__ float tf32_rn(float x) {
    float y; asm("cvt.rna.tf32.f32 %0, %1;" : "=f"(y) : "f"(x)); return y;
}
__device__ __forceinline__ void cp16(uint32_t dst, const void* src) {
    asm volatile("cp.async.cg.shared.global [%0], [%1], 16;"
                 :: "r"(dst), "l"(__cvta_generic_to_global(src)));
}
__device__ __forceinline__ uint32_t smem_u32(const void* p) {
    uint32_t a;
    asm("{ .reg .u64 t; cvta.to.shared.u64 t, %1; cvt.u32.u64 %0, t; }"
        : "=r"(a) : "l"(p));
    return a;
}
__device__ __forceinline__ uint32_t swz128(uint32_t off) {
    return off ^ ((off >> 3) & 0x70);
}
__device__ __forceinline__ uint32_t swz64(uint32_t off) {
    return off ^ ((off >> 3) & 0x30);
}

#define LDSM4(r0, r1, r2, r3, addr) \
    asm volatile("ldmatrix.sync.aligned.m8n8.x4.shared.b16 {%0,%1,%2,%3}, [%4];" \
        : "=r"(r0), "=r"(r1), "=r"(r2), "=r"(r3) : "r"(addr))

#define MMA_TF32U(d, a0, a1, a2, a3, b0, b1) \
    asm volatile( \
        "mma.sync.aligned.m16n8k8.row.col.f32.tf32.tf32.f32 " \
        "{%0,%1,%2,%3}, {%4,%5,%6,%7}, {%8,%9}, {%0,%1,%2,%3};" \
        : "+f"((d)[0]), "+f"((d)[1]), "+f"((d)[2]), "+f"((d)[3]) \
        : "r"(a0), "r"(a1), "r"(a2), "r"(a3), "r"(b0), "r"(b1))

#define MMA_BF16(d, a0, a1, a2, a3, b0, b1) \
    asm volatile( \
        "mma.sync.aligned.m16n8k16.row.col.f32.bf16.bf16.f32 " \
        "{%0,%1,%2,%3}, {%4,%5,%6,%7}, {%8,%9}, {%0,%1,%2,%3};" \
        : "+f"((d)[0]), "+f"((d)[1]), "+f"((d)[2]), "+f"((d)[3]) \
        : "r"(a0), "r"(a1), "r"(a2), "r"(a3), "r"(b0), "r"(b1))

// ---------------- prep ----------------------------------------------------
__global__ __launch_bounds__(256)
void prep_all(const float* __restrict__ w_mu,
              const float* __restrict__ w_sigma,
              const float* __restrict__ mu) {
    const int bid = blockIdx.x;
    const int tid = threadIdx.x;

    if (bid < PREP_W_BLOCKS) {
        __shared__ float t1[32][33];
        __shared__ float t2[32][33];
        __shared__ float red[3][256];
        const int bx = (bid & 127) * 32;   // n
        const int by = (bid >> 7) * 32;    // k
        const int tx = tid & 31, ty = tid >> 5;

        float s_log = 0.f, s_sp = 0.f, s_abs = 0.f;
#pragma unroll
        for (int i = 0; i < 4; i++) {
            int k = by + ty + i * 8;
            int n = bx + tx;
            float wm = w_mu[(size_t)k * SZ + n];
            float ws = w_sigma[(size_t)k * SZ + n];
            float sp = softplus_fast(ws);
            s_log += __logf(sp);
            s_sp  += sp;
            s_abs += fabsf(wm);
            t1[ty + i * 8][tx] = tf32_rn(wm);
            t2[ty + i * 8][tx] = sp;
        }
        __syncthreads();
        // packed transposed stores: 2 consecutive k per thread
        {
            const int no = tid >> 4;           // 0..15
            const int ko = (tid & 15) * 2;     // 0,2,..,30
#pragma unroll
            for (int i = 0; i < 2; i++) {
                int n = bx + no + i * 16;
                int k = by + ko;
                float a0 = t1[ko][no + i * 16];
                float a1 = t1[ko + 1][no + i * 16];
                *(float2*)&g_w1t[(size_t)n * SZ + k] = make_float2(a0, a1);
                float b0 = t2[ko][no + i * 16];
                float b1 = t2[ko + 1][no + i * 16];
                *(__nv_bfloat162*)&g_w2h[(size_t)n * SZ + k] =
                    __floats2bfloat162_rn(b0, b1);
            }
        }

        red[0][tid] = s_log; red[1][tid] = s_sp; red[2][tid] = s_abs;
        __syncthreads();
        for (int off = 128; off > 0; off >>= 1) {
            if (tid < off) {
                red[0][tid] += red[0][tid + off];
                red[1][tid] += red[1][tid + off];
                red[2][tid] += red[2][tid + off];
            }
            __syncthreads();
        }
        if (tid == 0) {
            g_part0[bid] = red[0][0];
            g_part1[bid] = red[1][0];
            g_part2[bid] = red[2][0];
        }
    } else {
        const int ab = bid - PREP_W_BLOCKS;      // 0..4095
        const float4* m4 = (const float4*)mu;
        __nv_bfloat162* a2h2 = (__nv_bfloat162*)g_a2h;
        const int i0 = ab * 1024;
#pragma unroll
        for (int t = 0; t < 4; t++) {
            int i = i0 + tid + t * 256;
            float4 x = m4[i];
            float2 p0 = make_float2(x.x * x.x, x.y * x.y);
            float2 p1 = make_float2(x.z * x.z, x.w * x.w);
            a2h2[i * 2]     = __float22bfloat162_rn(p0);
            a2h2[i * 2 + 1] = __float22bfloat162_rn(p1);
        }
    }
}

// ---------------- main dual GEMM: mu=tf32 k8, Sigma=bf16 k16 -----------------
// CTA: 128x64, 128 threads, 4 warps (2m x 2n), warp tile 64x32, 2 CTA/SM.
// A loaded raw from mu_in; tf32 rna rounding applied in-register post-LDSM.
// Block (0,0) also reduces the KL partials (prep done by stream order).
#define BM 128
#define BN 64
#define BK 32
#define NCHUNK (SZ / BK)       // 128

#define OFF_A   0u
#define OFF_W1  16384u
#define OFF_A2  24576u
#define OFF_W2  32768u
#define STAGE_BYTES 36864u
#define SMEM_TOTAL (3 * STAGE_BYTES)    // 110592, 2 CTAs/SM

__global__ __launch_bounds__(128, 2)
void gemm_dual(const float* __restrict__ mu,
               const float* __restrict__ b_mu,
               const float* __restrict__ b_sigma,
               float* __restrict__ out) {
    extern __shared__ char smem[];
    const uint32_t sb = smem_u32(smem);

    const int tid = threadIdx.x;

    // ---- block (0,0): fold the KL finalize (uses smem as scratch, then reuse)
    if (blockIdx.x == 0 && blockIdx.y == 0) {
        double* red = (double*)smem;   // 3 x 128 doubles = 3 KB
        double s0 = 0.0, s1 = 0.0, s2 = 0.0;
        for (int i = tid; i < PREP_W_BLOCKS; i += 128) {
            s0 += (double)g_part0[i];
            s1 += (double)g_part1[i];
            s2 += (double)g_part2[i];
        }
        red[tid] = s0; red[128 + tid] = s1; red[256 + tid] = s2;
        __syncthreads();
        for (int off = 64; off > 0; off >>= 1) {
            if (tid < off) {
                red[tid]       += red[tid + off];
                red[128 + tid] += red[128 + tid + off];
                red[256 + tid] += red[256 + tid + off];
            }
            __syncthreads();
        }
        if (tid == 0) {
            double mean_log = red[0] / (double)NW;
            double mean_sp  = red[128] / (double)NW;
            double kl = -0.5 * ((double)SZ * mean_log - red[256]
                                - (double)SZ * mean_sp);
            out[(size_t)2 * SZ * SZ] = (float)kl;
        }
        __syncthreads();   // scratch free before pipeline overwrites it
    }

    const int wid = tid >> 5;
    const int lid = tid & 31;
    const int lr  = lid >> 2;     // 0..7
    const int lc  = lid & 3;      // 0..3
    const int wm  = wid & 1;      // 0..1 (64 rows)
    const int wn  = wid >> 1;     // 0..1 (32 cols)
    const int m0 = blockIdx.y * BM;
    const int n0 = blockIdx.x * BN;

    const int lrow = lid & 7;
    const int lmat = lid >> 3;

    // Swizzled fragment addressing: addr = rowbase + ((cb + kbytes) ^ xr)
    uint32_t rbA[4], xrA[4];
#pragma unroll
    for (int mt = 0; mt < 4; mt++) {
        uint32_t r = (uint32_t)(wm * 64 + mt * 16 + (lmat & 1) * 8 + lrow);
        rbA[mt] = r * 128u;
        xrA[mt] = (r * 16u) & 0x70u;
    }
    const uint32_t cbA = (uint32_t)((lmat >> 1) * 16);
    uint32_t rbW[2], xrW[2];
#pragma unroll
    for (int ntp = 0; ntp < 2; ntp++) {
        uint32_t r = (uint32_t)(wn * 32 + ntp * 16 + (lmat >> 1) * 8 + lrow);
        rbW[ntp] = r * 128u;
        xrW[ntp] = (r * 16u) & 0x70u;
    }
    const uint32_t cbW = (uint32_t)((lmat & 1) * 16);
    uint32_t rbA2[4], xrA2[4];
#pragma unroll
    for (int mt = 0; mt < 4; mt++) {
        uint32_t r = (uint32_t)(wm * 64 + mt * 16 + (lmat & 1) * 8 + lrow);
        rbA2[mt] = r * 64u;
        xrA2[mt] = (r * 8u) & 0x30u;
    }
    const uint32_t cbA2 = (uint32_t)((lmat >> 1) * 16);
    uint32_t rbW2[2], xrW2[2];
#pragma unroll
    for (int ntp = 0; ntp < 2; ntp++) {
        uint32_t r = (uint32_t)(wn * 32 + ntp * 16 + (lmat >> 1) * 8 + lrow);
        rbW2[ntp] = r * 64u;
        xrW2[ntp] = (r * 8u) & 0x30u;
    }
    const uint32_t cbW2 = (uint32_t)((lmat & 1) * 16);

    float acc1[4][4][4];
    float acc2[4][4][4];
#pragma unroll
    for (int mt = 0; mt < 4; mt++)
#pragma unroll
        for (int nt = 0; nt < 4; nt++)
#pragma unroll
            for (int q = 0; q < 4; q++) { acc1[mt][nt][q] = 0.f; acc2[mt][nt][q] = 0.f; }

    // Stage loader: 18 x 16B cp.async per thread (128 threads)
    auto load_stage = [&](int chunk, int s) {
        const int k0 = chunk * BK;
        const uint32_t base = sb + (uint32_t)s * STAGE_BYTES;
#pragma unroll
        for (int i = 0; i < 8; i++) {           // A raw fp32: 128 rows x 8 c16
            int f = tid + i * 128;
            int r = f >> 3, cc = f & 7;
            cp16(base + OFF_A + swz128((uint32_t)(r * 128 + cc * 16)),
                 mu + (size_t)(m0 + r) * SZ + k0 + cc * 4);
        }
#pragma unroll
        for (int i = 0; i < 4; i++) {           // W1 tf32: 64 rows x 8 c16
            int f = tid + i * 128;
            int r = f >> 3, cc = f & 7;
            cp16(base + OFF_W1 + swz128((uint32_t)(r * 128 + cc * 16)),
                 g_w1t + (size_t)(n0 + r) * SZ + k0 + cc * 4);
        }
#pragma unroll
        for (int i = 0; i < 4; i++) {           // A2h bf16: 128 rows x 4 u16
            int f = tid + i * 128;
            int r = f >> 2, u = f & 3;
            cp16(base + OFF_A2 + swz64((uint32_t)(r * 64 + u * 16)),
                 (const char*)g_a2h + ((size_t)(m0 + r) * SZ + k0) * 2 + u * 16);
        }
#pragma unroll
        for (int i = 0; i < 2; i++) {           // W2h bf16: 64 rows x 4 u16
            int f = tid + i * 128;
            int r = f >> 2, u = f & 3;
            cp16(base + OFF_W2 + swz64((uint32_t)(r * 64 + u * 16)),
                 (const char*)g_w2h + ((size_t)(n0 + r) * SZ + k0) * 2 + u * 16);
        }
        asm volatile("cp.async.commit_group;" ::: "memory");
    };

    load_stage(0, 0);
    load_stage(1, 1);

    for (int c = 0; c < NCHUNK; c++) {
        const int s = c % 3;
        asm volatile("cp.async.wait_group 1;" ::: "memory");
        __syncthreads();
        if (c + 2 < NCHUNK) load_stage(c + 2, (c + 2) % 3);
        else asm volatile("cp.async.commit_group;" ::: "memory");

        const uint32_t stA  = sb + (uint32_t)s * STAGE_BYTES + OFF_A;
        const uint32_t stW1 = sb + (uint32_t)s * STAGE_BYTES + OFF_W1;
        const uint32_t stA2 = sb + (uint32_t)s * STAGE_BYTES + OFF_A2;
        const uint32_t stW2 = sb + (uint32_t)s * STAGE_BYTES + OFF_W2;

#pragma unroll
        for (int j = 0; j < 2; j++) {
            // ---- mu path: tf32 k8, ksteps 2j, 2j+1 (rna rounding in-register)
#pragma unroll
            for (int ksub = 0; ksub < 2; ksub++) {
                const uint32_t kb = (uint32_t)((j * 2 + ksub) * 32);
                uint32_t af[4][4];
#pragma unroll
                for (int mt = 0; mt < 4; mt++)
                    LDSM4(af[mt][0], af[mt][1], af[mt][2], af[mt][3],
                          stA + rbA[mt] + ((cbA + kb) ^ xrA[mt]));
#pragma unroll
                for (int mt = 0; mt < 4; mt++)
#pragma unroll
                    for (int q = 0; q < 4; q++)
                        af[mt][q] = __float_as_uint(
                            tf32_rn(__uint_as_float(af[mt][q])));
#pragma unroll
                for (int ntp = 0; ntp < 2; ntp++) {
                    uint32_t wf[4];
                    LDSM4(wf[0], wf[1], wf[2], wf[3],
                          stW1 + rbW[ntp] + ((cbW + kb) ^ xrW[ntp]));
#pragma unroll
                    for (int h = 0; h < 2; h++) {
                        const int nt = ntp * 2 + h;
#pragma unroll
                        for (int mt = 0; mt < 4; mt++)
                            MMA_TF32U(acc1[mt][nt], af[mt][0], af[mt][1],
                                      af[mt][2], af[mt][3],
                                      wf[h * 2], wf[h * 2 + 1]);
                    }
                }
            }
            // ---- Sigma path: bf16 k16, kstep j ----
            {
                const uint32_t kb = (uint32_t)(j * 32);
                uint32_t a2f[4][4];
#pragma unroll
                for (int mt = 0; mt < 4; mt++)
                    LDSM4(a2f[mt][0], a2f[mt][1], a2f[mt][2], a2f[mt][3],
                          stA2 + rbA2[mt] + ((cbA2 + kb) ^ xrA2[mt]));
#pragma unroll
                for (int ntp = 0; ntp < 2; ntp++) {
                    uint32_t wf[4];
                    LDSM4(wf[0], wf[1], wf[2], wf[3],
                          stW2 + rbW2[ntp] + ((cbW2 + kb) ^ xrW2[ntp]));
#pragma unroll
                    for (int nb = 0; nb < 2; nb++) {
                        const int nt = ntp * 2 + nb;
#pragma unroll
                        for (int mt = 0; mt < 4; mt++)
                            MMA_BF16(acc2[mt][nt], a2f[mt][0], a2f[mt][1],
                                     a2f[mt][2], a2f[mt][3],
                                     wf[nb * 2], wf[nb * 2 + 1]);
                    }
                }
            }
        }
    }

    // ---------------- epilogue ----------------
    float* o1 = out;
    float* o2 = out + (size_t)SZ * SZ;
#pragma unroll
    for (int nt = 0; nt < 4; nt++) {
        int col = n0 + wn * 32 + nt * 8 + lc * 2;
        float bm0 = b_mu[col],  bm1 = b_mu[col + 1];
        float bs0 = softplusf(b_sigma[col]), bs1 = softplusf(b_sigma[col + 1]);
#pragma unroll
        for (int mt = 0; mt < 4; mt++) {
            int row = m0 + wm * 64 + mt * 16 + lr;
            float2 v;
            v.x = acc1[mt][nt][0] + bm0; v.y = acc1[mt][nt][1] + bm1;
            *(float2*)(o1 + (size_t)row * SZ + col) = v;
            v.x = acc1[mt][nt][2] + bm0; v.y = acc1[mt][nt][3] + bm1;
            *(float2*)(o1 + (size_t)(row + 8) * SZ + col) = v;
            v.x = acc2[mt][nt][0] + bs0; v.y = acc2[mt][nt][1] + bs1;
            *(float2*)(o2 + (size_t)row * SZ + col) = v;
            v.x = acc2[mt][nt][2] + bs0; v.y = acc2[mt][nt][3] + bs1;
            *(float2*)(o2 + (size_t)(row + 8) * SZ + col) = v;
        }
    }
}

// ---------------- launch -----------------------------------------------------
extern "C" void kernel_launch(void* const* d_in, const int* in_sizes, int n_in,
                              void* d_out, int out_size) {
    const float* mu_in   = (const float*)d_in[0];
    // d_in[1] = sigma_in : unused by the reference outputs
    const float* w_mu    = (const float*)d_in[2];
    const float* w_sigma = (const float*)d_in[3];
    const float* b_mu    = (const float*)d_in[4];
    const float* b_sigma = (const float*)d_in[5];
    float* out = (float*)d_out;

    cudaFuncSetAttribute(gemm_dual, cudaFuncAttributeMaxDynamicSharedMemorySize,
                         SMEM_TOTAL);

    prep_all<<<PREP_W_BLOCKS + 4096, 256>>>(w_mu, w_sigma, mu_in);
    gemm_dual<<<dim3(SZ / BN, SZ / BM), 128, SMEM_TOTAL>>>(mu_in, b_mu, b_sigma, out);
}

// round 16
// speedup vs baseline: 1.0629x; 1.0629x over previous
#include <cuda_runtime.h>
#include <cuda_bf16.h>
#include <math.h>
#include <stdint.h>

#define SZ 4096
#define NW (SZ*SZ)

// ---------------- scratch (static __device__, no runtime alloc) -------------
__device__ __align__(16) float         g_a[NW];    // tf32-rounded mu_in [B][K]
__device__ __align__(16) float         g_w1t[NW];  // tf32-rounded w_mu^T [N][K]
__device__ __align__(16) __nv_bfloat16 g_a2h[NW];  // bf16(mu^2)        [B][K]
__device__ __align__(16) __nv_bfloat16 g_w2h[NW];  // bf16(sp(w_sig))^T [N][K]
#define PREP_W_BLOCKS 16384
__device__ float g_part0[PREP_W_BLOCKS];   // sum log(sp)
__device__ float g_part1[PREP_W_BLOCKS];   // sum sp
__device__ float g_part2[PREP_W_BLOCKS];   // sum |w_mu|

__device__ __forceinline__ float softplus_fast(float x) {
    return log1pf(__expf(x));   // args <= -2.2: no overflow
}
__device__ __forceinline__ float softplusf(float x) {
    return x > 20.0f ? x : log1pf(expf(x));
}
__device__ __forceinline__ float tf32_rn(float x) {
    float y; asm("cvt.rna.tf32.f32 %0, %1;" : "=f"(y) : "f"(x)); return y;
}
__device__ __forceinline__ void cp16(uint32_t dst, const void* src) {
    asm volatile("cp.async.cg.shared.global [%0], [%1], 16;"
                 :: "r"(dst), "l"(__cvta_generic_to_global(src)));
}
__device__ __forceinline__ uint32_t smem_u32(const void* p) {
    uint32_t a;
    asm("{ .reg .u64 t; cvta.to.shared.u64 t, %1; cvt.u32.u64 %0, t; }"
        : "=r"(a) : "l"(p));
    return a;
}
__device__ __forceinline__ uint32_t swz128(uint32_t off) {
    return off ^ ((off >> 3) & 0x70);
}
__device__ __forceinline__ uint32_t swz64(uint32_t off) {
    return off ^ ((off >> 3) & 0x30);
}

#define LDSM4(r0, r1, r2, r3, addr) \
    asm volatile("ldmatrix.sync.aligned.m8n8.x4.shared.b16 {%0,%1,%2,%3}, [%4];" \
        : "=r"(r0), "=r"(r1), "=r"(r2), "=r"(r3) : "r"(addr))

#define MMA_TF32U(d, a0, a1, a2, a3, b0, b1) \
    asm volatile( \
        "mma.sync.aligned.m16n8k8.row.col.f32.tf32.tf32.f32 " \
        "{%0,%1,%2,%3}, {%4,%5,%6,%7}, {%8,%9}, {%0,%1,%2,%3};" \
        : "+f"((d)[0]), "+f"((d)[1]), "+f"((d)[2]), "+f"((d)[3]) \
        : "r"(a0), "r"(a1), "r"(a2), "r"(a3), "r"(b0), "r"(b1))

#define MMA_BF16(d, a0, a1, a2, a3, b0, b1) \
    asm volatile( \
        "mma.sync.aligned.m16n8k16.row.col.f32.bf16.bf16.f32 " \
        "{%0,%1,%2,%3}, {%4,%5,%6,%7}, {%8,%9}, {%0,%1,%2,%3};" \
        : "+f"((d)[0]), "+f"((d)[1]), "+f"((d)[2]), "+f"((d)[3]) \
        : "r"(a0), "r"(a1), "r"(a2), "r"(a3), "r"(b0), "r"(b1))

// ---------------- prep ----------------------------------------------------
__global__ __launch_bounds__(256)
void prep_all(const float* __restrict__ w_mu,
              const float* __restrict__ w_sigma,
              const float* __restrict__ mu) {
    const int bid = blockIdx.x;
    const int tid = threadIdx.x;

    if (bid < PREP_W_BLOCKS) {
        __shared__ float t1[32][33];
        __shared__ float t2[32][33];
        __shared__ float red[3][256];
        const int bx = (bid & 127) * 32;   // n
        const int by = (bid >> 7) * 32;    // k
        const int tx = tid & 31, ty = tid >> 5;

        float s_log = 0.f, s_sp = 0.f, s_abs = 0.f;
#pragma unroll
        for (int i = 0; i < 4; i++) {
            int k = by + ty + i * 8;
            int n = bx + tx;
            float wm = w_mu[(size_t)k * SZ + n];
            float ws = w_sigma[(size_t)k * SZ + n];
            float sp = softplus_fast(ws);
            s_log += __logf(sp);
            s_sp  += sp;
            s_abs += fabsf(wm);
            t1[ty + i * 8][tx] = tf32_rn(wm);
            t2[ty + i * 8][tx] = sp;
        }
        __syncthreads();
        // packed transposed stores: 2 consecutive k per thread
        {
            const int no = tid >> 4;           // 0..15
            const int ko = (tid & 15) * 2;     // 0,2,..,30
#pragma unroll
            for (int i = 0; i < 2; i++) {
                int n = bx + no + i * 16;
                int k = by + ko;
                float a0 = t1[ko][no + i * 16];
                float a1 = t1[ko + 1][no + i * 16];
                *(float2*)&g_w1t[(size_t)n * SZ + k] = make_float2(a0, a1);
                float b0 = t2[ko][no + i * 16];
                float b1 = t2[ko + 1][no + i * 16];
                *(__nv_bfloat162*)&g_w2h[(size_t)n * SZ + k] =
                    __floats2bfloat162_rn(b0, b1);
            }
        }

        red[0][tid] = s_log; red[1][tid] = s_sp; red[2][tid] = s_abs;
        __syncthreads();
        for (int off = 128; off > 0; off >>= 1) {
            if (tid < off) {
                red[0][tid] += red[0][tid + off];
                red[1][tid] += red[1][tid + off];
                red[2][tid] += red[2][tid + off];
            }
            __syncthreads();
        }
        if (tid == 0) {
            g_part0[bid] = red[0][0];
            g_part1[bid] = red[1][0];
            g_part2[bid] = red[2][0];
        }
    } else {
        const int ab = bid - PREP_W_BLOCKS;      // 0..4095
        const float4* m4 = (const float4*)mu;
        float4* a4 = (float4*)g_a;
        __nv_bfloat162* a2h2 = (__nv_bfloat162*)g_a2h;
        const int i0 = ab * 1024;
#pragma unroll
        for (int t = 0; t < 4; t++) {
            int i = i0 + tid + t * 256;
            float4 x = m4[i];
            float4 a;
            a.x = tf32_rn(x.x); a.y = tf32_rn(x.y);
            a.z = tf32_rn(x.z); a.w = tf32_rn(x.w);
            a4[i] = a;
            float2 p0 = make_float2(x.x * x.x, x.y * x.y);
            float2 p1 = make_float2(x.z * x.z, x.w * x.w);
            a2h2[i * 2]     = __float22bfloat162_rn(p0);
            a2h2[i * 2 + 1] = __float22bfloat162_rn(p1);
        }
    }
}

// ---------------- main dual GEMM: mu=tf32 k8, Sigma=bf16 k16 -----------------
// CTA: 128x64, 128 threads, 4 warps (2m x 2n), warp tile 64x32, 2 CTA/SM.
// Swizzled smem, 3-stage cp.async (R14 body). Block (0,0) folds the KL
// finalize (prep results visible by stream order).
#define BM 128
#define BN 64
#define BK 32
#define NCHUNK (SZ / BK)       // 128

#define OFF_A   0u
#define OFF_W1  16384u
#define OFF_A2  24576u
#define OFF_W2  32768u
#define STAGE_BYTES 36864u
#define SMEM_TOTAL (3 * STAGE_BYTES)    // 110592, 2 CTAs/SM

__global__ __launch_bounds__(128, 2)
void gemm_dual(const float* __restrict__ b_mu,
               const float* __restrict__ b_sigma,
               float* __restrict__ out) {
    extern __shared__ char smem[];
    const uint32_t sb = smem_u32(smem);

    const int tid = threadIdx.x;

    // ---- block (0,0): fold the KL finalize (smem scratch, then reused)
    if (blockIdx.x == 0 && blockIdx.y == 0) {
        double* red = (double*)smem;   // 3 x 128 doubles = 3 KB
        double s0 = 0.0, s1 = 0.0, s2 = 0.0;
        for (int i = tid; i < PREP_W_BLOCKS; i += 128) {
            s0 += (double)g_part0[i];
            s1 += (double)g_part1[i];
            s2 += (double)g_part2[i];
        }
        red[tid] = s0; red[128 + tid] = s1; red[256 + tid] = s2;
        __syncthreads();
        for (int off = 64; off > 0; off >>= 1) {
            if (tid < off) {
                red[tid]       += red[tid + off];
                red[128 + tid] += red[128 + tid + off];
                red[256 + tid] += red[256 + tid + off];
            }
            __syncthreads();
        }
        if (tid == 0) {
            double mean_log = red[0] / (double)NW;
            double mean_sp  = red[128] / (double)NW;
            double kl = -0.5 * ((double)SZ * mean_log - red[256]
                                - (double)SZ * mean_sp);
            out[(size_t)2 * SZ * SZ] = (float)kl;
        }
        __syncthreads();   // scratch free before pipeline overwrites it
    }

    const int wid = tid >> 5;
    const int lid = tid & 31;
    const int lr  = lid >> 2;     // 0..7
    const int lc  = lid & 3;      // 0..3
    const int wm  = wid & 1;      // 0..1 (64 rows)
    const int wn  = wid >> 1;     // 0..1 (32 cols)
    const int m0 = blockIdx.y * BM;
    const int n0 = blockIdx.x * BN;

    const int lrow = lid & 7;
    const int lmat = lid >> 3;

    // Swizzled fragment addressing: addr = rowbase + ((cb + kbytes) ^ xr)
    uint32_t rbA[4], xrA[4];
#pragma unroll
    for (int mt = 0; mt < 4; mt++) {
        uint32_t r = (uint32_t)(wm * 64 + mt * 16 + (lmat & 1) * 8 + lrow);
        rbA[mt] = r * 128u;
        xrA[mt] = (r * 16u) & 0x70u;
    }
    const uint32_t cbA = (uint32_t)((lmat >> 1) * 16);
    uint32_t rbW[2], xrW[2];
#pragma unroll
    for (int ntp = 0; ntp < 2; ntp++) {
        uint32_t r = (uint32_t)(wn * 32 + ntp * 16 + (lmat >> 1) * 8 + lrow);
        rbW[ntp] = r * 128u;
        xrW[ntp] = (r * 16u) & 0x70u;
    }
    const uint32_t cbW = (uint32_t)((lmat & 1) * 16);
    uint32_t rbA2[4], xrA2[4];
#pragma unroll
    for (int mt = 0; mt < 4; mt++) {
        uint32_t r = (uint32_t)(wm * 64 + mt * 16 + (lmat & 1) * 8 + lrow);
        rbA2[mt] = r * 64u;
        xrA2[mt] = (r * 8u) & 0x30u;
    }
    const uint32_t cbA2 = (uint32_t)((lmat >> 1) * 16);
    uint32_t rbW2[2], xrW2[2];
#pragma unroll
    for (int ntp = 0; ntp < 2; ntp++) {
        uint32_t r = (uint32_t)(wn * 32 + ntp * 16 + (lmat >> 1) * 8 + lrow);
        rbW2[ntp] = r * 64u;
        xrW2[ntp] = (r * 8u) & 0x30u;
    }
    const uint32_t cbW2 = (uint32_t)((lmat & 1) * 16);

    float acc1[4][4][4];
    float acc2[4][4][4];
#pragma unroll
    for (int mt = 0; mt < 4; mt++)
#pragma unroll
        for (int nt = 0; nt < 4; nt++)
#pragma unroll
            for (int q = 0; q < 4; q++) { acc1[mt][nt][q] = 0.f; acc2[mt][nt][q] = 0.f; }

    // Stage loader: 18 x 16B cp.async per thread (128 threads)
    auto load_stage = [&](int chunk, int s) {
        const int k0 = chunk * BK;
        const uint32_t base = sb + (uint32_t)s * STAGE_BYTES;
#pragma unroll
        for (int i = 0; i < 8; i++) {           // A tf32: 128 rows x 8 c16
            int f = tid + i * 128;
            int r = f >> 3, cc = f & 7;
            cp16(base + OFF_A + swz128((uint32_t)(r * 128 + cc * 16)),
                 g_a + (size_t)(m0 + r) * SZ + k0 + cc * 4);
        }
#pragma unroll
        for (int i = 0; i < 4; i++) {           // W1 tf32: 64 rows x 8 c16
            int f = tid + i * 128;
            int r = f >> 3, cc = f & 7;
            cp16(base + OFF_W1 + swz128((uint32_t)(r * 128 + cc * 16)),
                 g_w1t + (size_t)(n0 + r) * SZ + k0 + cc * 4);
        }
#pragma unroll
        for (int i = 0; i < 4; i++) {           // A2h bf16: 128 rows x 4 u16
            int f = tid + i * 128;
            int r = f >> 2, u = f & 3;
            cp16(base + OFF_A2 + swz64((uint32_t)(r * 64 + u * 16)),
                 (const char*)g_a2h + ((size_t)(m0 + r) * SZ + k0) * 2 + u * 16);
        }
#pragma unroll
        for (int i = 0; i < 2; i++) {           // W2h bf16: 64 rows x 4 u16
            int f = tid + i * 128;
            int r = f >> 2, u = f & 3;
            cp16(base + OFF_W2 + swz64((uint32_t)(r * 64 + u * 16)),
                 (const char*)g_w2h + ((size_t)(n0 + r) * SZ + k0) * 2 + u * 16);
        }
        asm volatile("cp.async.commit_group;" ::: "memory");
    };

    load_stage(0, 0);
    load_stage(1, 1);

    for (int c = 0; c < NCHUNK; c++) {
        const int s = c % 3;
        asm volatile("cp.async.wait_group 1;" ::: "memory");
        __syncthreads();
        if (c + 2 < NCHUNK) load_stage(c + 2, (c + 2) % 3);
        else asm volatile("cp.async.commit_group;" ::: "memory");

        const uint32_t stA  = sb + (uint32_t)s * STAGE_BYTES + OFF_A;
        const uint32_t stW1 = sb + (uint32_t)s * STAGE_BYTES + OFF_W1;
        const uint32_t stA2 = sb + (uint32_t)s * STAGE_BYTES + OFF_A2;
        const uint32_t stW2 = sb + (uint32_t)s * STAGE_BYTES + OFF_W2;

#pragma unroll
        for (int j = 0; j < 2; j++) {
            // ---- mu path: tf32 k8, ksteps 2j, 2j+1 ----
#pragma unroll
            for (int ksub = 0; ksub < 2; ksub++) {
                const uint32_t kb = (uint32_t)((j * 2 + ksub) * 32);
                uint32_t af[4][4];
#pragma unroll
                for (int mt = 0; mt < 4; mt++)
                    LDSM4(af[mt][0], af[mt][1], af[mt][2], af[mt][3],
                          stA + rbA[mt] + ((cbA + kb) ^ xrA[mt]));
#pragma unroll
                for (int ntp = 0; ntp < 2; ntp++) {
                    uint32_t wf[4];
                    LDSM4(wf[0], wf[1], wf[2], wf[3],
                          stW1 + rbW[ntp] + ((cbW + kb) ^ xrW[ntp]));
#pragma unroll
                    for (int h = 0; h < 2; h++) {
                        const int nt = ntp * 2 + h;
#pragma unroll
                        for (int mt = 0; mt < 4; mt++)
                            MMA_TF32U(acc1[mt][nt], af[mt][0], af[mt][1],
                                      af[mt][2], af[mt][3],
                                      wf[h * 2], wf[h * 2 + 1]);
                    }
                }
            }
            // ---- Sigma path: bf16 k16, kstep j ----
            {
                const uint32_t kb = (uint32_t)(j * 32);
                uint32_t a2f[4][4];
#pragma unroll
                for (int mt = 0; mt < 4; mt++)
                    LDSM4(a2f[mt][0], a2f[mt][1], a2f[mt][2], a2f[mt][3],
                          stA2 + rbA2[mt] + ((cbA2 + kb) ^ xrA2[mt]));
#pragma unroll
                for (int ntp = 0; ntp < 2; ntp++) {
                    uint32_t wf[4];
                    LDSM4(wf[0], wf[1], wf[2], wf[3],
                          stW2 + rbW2[ntp] + ((cbW2 + kb) ^ xrW2[ntp]));
#pragma unroll
                    for (int nb = 0; nb < 2; nb++) {
                        const int nt = ntp * 2 + nb;
#pragma unroll
                        for (int mt = 0; mt < 4; mt++)
                            MMA_BF16(acc2[mt][nt], a2f[mt][0], a2f[mt][1],
                                     a2f[mt][2], a2f[mt][3],
                                     wf[nb * 2], wf[nb * 2 + 1]);
                    }
                }
            }
        }
    }

    // ---------------- epilogue ----------------
    float* o1 = out;
    float* o2 = out + (size_t)SZ * SZ;
#pragma unroll
    for (int nt = 0; nt < 4; nt++) {
        int col = n0 + wn * 32 + nt * 8 + lc * 2;
        float bm0 = b_mu[col],  bm1 = b_mu[col + 1];
        float bs0 = softplusf(b_sigma[col]), bs1 = softplusf(b_sigma[col + 1]);
#pragma unroll
        for (int mt = 0; mt < 4; mt++) {
            int row = m0 + wm * 64 + mt * 16 + lr;
            float2 v;
            v.x = acc1[mt][nt][0] + bm0; v.y = acc1[mt][nt][1] + bm1;
            *(float2*)(o1 + (size_t)row * SZ + col) = v;
            v.x = acc1[mt][nt][2] + bm0; v.y = acc1[mt][nt][3] + bm1;
            *(float2*)(o1 + (size_t)(row + 8) * SZ + col) = v;
            v.x = acc2[mt][nt][0] + bs0; v.y = acc2[mt][nt][1] + bs1;
            *(float2*)(o2 + (size_t)row * SZ + col) = v;
            v.x = acc2[mt][nt][2] + bs0; v.y = acc2[mt][nt][3] + bs1;
            *(float2*)(o2 + (size_t)(row + 8) * SZ + col) = v;
        }
    }
}

// ---------------- launch -----------------------------------------------------
extern "C" void kernel_launch(void* const* d_in, const int* in_sizes, int n_in,
                              void* d_out, int out_size) {
    const float* mu_in   = (const float*)d_in[0];
    // d_in[1] = sigma_in : unused by the reference outputs
    const float* w_mu    = (const float*)d_in[2];
    const float* w_sigma = (const float*)d_in[3];
    const float* b_mu    = (const float*)d_in[4];
    const float* b_sigma = (const float*)d_in[5];
    float* out = (float*)d_out;

    cudaFuncSetAttribute(gemm_dual, cudaFuncAttributeMaxDynamicSharedMemorySize,
                         SMEM_TOTAL);

    prep_all<<<PREP_W_BLOCKS + 4096, 256>>>(w_mu, w_sigma, mu_in);
    gemm_dual<<<dim3(SZ / BN, SZ / BM), 128, SMEM_TOTAL>>>(b_mu, b_sigma, out);
}

// round 17
// speedup vs baseline: 1.1406x; 1.0731x over previous
#include <cuda_runtime.h>
#include <cuda_bf16.h>
#include <math.h>
#include <stdint.h>

#define SZ 4096
#define NW (SZ*SZ)

// ---------------- scratch (static __device__, no runtime alloc) -------------
__device__ __align__(16) float         g_a[NW];    // tf32-rounded mu_in [B][K]
__device__ __align__(16) float         g_w1t[NW];  // tf32-rounded w_mu^T [N][K]
__device__ __align__(16) __nv_bfloat16 g_a2h[NW];  // bf16(mu^2)        [B][K]
__device__ __align__(16) __nv_bfloat16 g_w2h[NW];  // bf16(sp(w_sig))^T [N][K]
#define PREP_W_BLOCKS 16384
__device__ float g_part0[PREP_W_BLOCKS];   // sum log(sp)
__device__ float g_part1[PREP_W_BLOCKS];   // sum sp
__device__ float g_part2[PREP_W_BLOCKS];   // sum |w_mu|

__device__ __forceinline__ float softplus_fast(float x) {
    return log1pf(__expf(x));   // args <= -2.2: no overflow
}
__device__ __forceinline__ float softplusf(float x) {
    return x > 20.0f ? x : log1pf(expf(x));
}
__device__ __forceinline__ float tf32_rn(float x) {
    float y; asm("cvt.rna.tf32.f32 %0, %1;" : "=f"(y) : "f"(x)); return y;
}
__device__ __forceinline__ void cp16(uint32_t dst, const void* src) {
    asm volatile("cp.async.cg.shared.global [%0], [%1], 16;"
                 :: "r"(dst), "l"(__cvta_generic_to_global(src)));
}
__device__ __forceinline__ uint32_t smem_u32(const void* p) {
    uint32_t a;
    asm("{ .reg .u64 t; cvta.to.shared.u64 t, %1; cvt.u32.u64 %0, t; }"
        : "=r"(a) : "l"(p));
    return a;
}
__device__ __forceinline__ uint32_t swz128(uint32_t off) {
    return off ^ ((off >> 3) & 0x70);
}
__device__ __forceinline__ uint32_t swz64(uint32_t off) {
    return off ^ ((off >> 3) & 0x30);
}

#define LDSM4(r0, r1, r2, r3, addr) \
    asm volatile("ldmatrix.sync.aligned.m8n8.x4.shared.b16 {%0,%1,%2,%3}, [%4];" \
        : "=r"(r0), "=r"(r1), "=r"(r2), "=r"(r3) : "r"(addr))

#define MMA_TF32U(d, a0, a1, a2, a3, b0, b1) \
    asm volatile( \
        "mma.sync.aligned.m16n8k8.row.col.f32.tf32.tf32.f32 " \
        "{%0,%1,%2,%3}, {%4,%5,%6,%7}, {%8,%9}, {%0,%1,%2,%3};" \
        : "+f"((d)[0]), "+f"((d)[1]), "+f"((d)[2]), "+f"((d)[3]) \
        : "r"(a0), "r"(a1), "r"(a2), "r"(a3), "r"(b0), "r"(b1))

#define MMA_BF16(d, a0, a1, a2, a3, b0, b1) \
    asm volatile( \
        "mma.sync.aligned.m16n8k16.row.col.f32.bf16.bf16.f32 " \
        "{%0,%1,%2,%3}, {%4,%5,%6,%7}, {%8,%9}, {%0,%1,%2,%3};" \
        : "+f"((d)[0]), "+f"((d)[1]), "+f"((d)[2]), "+f"((d)[3]) \
        : "r"(a0), "r"(a1), "r"(a2), "r"(a3), "r"(b0), "r"(b1))

// ---------------- prep ----------------------------------------------------
__global__ __launch_bounds__(256)
void prep_all(const float* __restrict__ w_mu,
              const float* __restrict__ w_sigma,
              const float* __restrict__ mu) {
    const int bid = blockIdx.x;
    const int tid = threadIdx.x;

    if (bid < PREP_W_BLOCKS) {
        __shared__ float t1[32][33];
        __shared__ float t2[32][33];
        __shared__ float wr[3][8];
        const int bx = (bid & 127) * 32;   // n
        const int by = (bid >> 7) * 32;    // k
        const int tx = tid & 31, ty = tid >> 5;

        float s_log = 0.f, s_sp = 0.f, s_abs = 0.f;
#pragma unroll
        for (int i = 0; i < 4; i++) {
            int k = by + ty + i * 8;
            int n = bx + tx;
            float wm = w_mu[(size_t)k * SZ + n];
            float ws = w_sigma[(size_t)k * SZ + n];
            float sp = softplus_fast(ws);
            s_log += __logf(sp);
            s_sp  += sp;
            s_abs += fabsf(wm);
            t1[ty + i * 8][tx] = tf32_rn(wm);
            t2[ty + i * 8][tx] = sp;
        }
        // warp-shuffle reduction of the three KL sums
#pragma unroll
        for (int off = 16; off > 0; off >>= 1) {
            s_log += __shfl_xor_sync(0xFFFFFFFFu, s_log, off);
            s_sp  += __shfl_xor_sync(0xFFFFFFFFu, s_sp,  off);
            s_abs += __shfl_xor_sync(0xFFFFFFFFu, s_abs, off);
        }
        if (tx == 0) { wr[0][ty] = s_log; wr[1][ty] = s_sp; wr[2][ty] = s_abs; }
        __syncthreads();

        // packed transposed stores: 2 consecutive k per thread
        {
            const int no = tid >> 4;           // 0..15
            const int ko = (tid & 15) * 2;     // 0,2,..,30
#pragma unroll
            for (int i = 0; i < 2; i++) {
                int n = bx + no + i * 16;
                int k = by + ko;
                float a0 = t1[ko][no + i * 16];
                float a1 = t1[ko + 1][no + i * 16];
                *(float2*)&g_w1t[(size_t)n * SZ + k] = make_float2(a0, a1);
                float b0 = t2[ko][no + i * 16];
                float b1 = t2[ko + 1][no + i * 16];
                *(__nv_bfloat162*)&g_w2h[(size_t)n * SZ + k] =
                    __floats2bfloat162_rn(b0, b1);
            }
        }

        if (tid == 0) {
            float t0 = 0.f, u1 = 0.f, u2 = 0.f;
#pragma unroll
            for (int i = 0; i < 8; i++) {
                t0 += wr[0][i]; u1 += wr[1][i]; u2 += wr[2][i];
            }
            g_part0[bid] = t0;
            g_part1[bid] = u1;
            g_part2[bid] = u2;
        }
    } else {
        const int ab = bid - PREP_W_BLOCKS;      // 0..4095
        const float4* m4 = (const float4*)mu;
        float4* a4 = (float4*)g_a;
        __nv_bfloat162* a2h2 = (__nv_bfloat162*)g_a2h;
        const int i0 = ab * 1024;
#pragma unroll
        for (int t = 0; t < 4; t++) {
            int i = i0 + tid + t * 256;
            float4 x = m4[i];
            float4 a;
            a.x = tf32_rn(x.x); a.y = tf32_rn(x.y);
            a.z = tf32_rn(x.z); a.w = tf32_rn(x.w);
            a4[i] = a;
            float2 p0 = make_float2(x.x * x.x, x.y * x.y);
            float2 p1 = make_float2(x.z * x.z, x.w * x.w);
            a2h2[i * 2]     = __float22bfloat162_rn(p0);
            a2h2[i * 2 + 1] = __float22bfloat162_rn(p1);
        }
    }
}

// ---------------- main dual GEMM: mu=tf32 k8, Sigma=bf16 k16 -----------------
// CTA: 128x64, 128 threads, 4 warps (2m x 2n), warp tile 64x32, 2 CTA/SM.
// Swizzled smem, 3-stage cp.async. Post-barrier order: mu kstep0 first, then
// the next-stage prefetch burst (2-chunk slack). Block (0,0) folds KL finalize.
#define BM 128
#define BN 64
#define BK 32
#define NCHUNK (SZ / BK)       // 128

#define OFF_A   0u
#define OFF_W1  16384u
#define OFF_A2  24576u
#define OFF_W2  32768u
#define STAGE_BYTES 36864u
#define SMEM_TOTAL (3 * STAGE_BYTES)    // 110592, 2 CTAs/SM

__global__ __launch_bounds__(128, 2)
void gemm_dual(const float* __restrict__ b_mu,
               const float* __restrict__ b_sigma,
               float* __restrict__ out) {
    extern __shared__ char smem[];
    const uint32_t sb = smem_u32(smem);

    const int tid = threadIdx.x;

    // ---- block (0,0): fold the KL finalize (smem scratch, then reused)
    if (blockIdx.x == 0 && blockIdx.y == 0) {
        double* red = (double*)smem;   // 3 x 128 doubles = 3 KB
        double s0 = 0.0, s1 = 0.0, s2 = 0.0;
        for (int i = tid; i < PREP_W_BLOCKS; i += 128) {
            s0 += (double)g_part0[i];
            s1 += (double)g_part1[i];
            s2 += (double)g_part2[i];
        }
        red[tid] = s0; red[128 + tid] = s1; red[256 + tid] = s2;
        __syncthreads();
        for (int off = 64; off > 0; off >>= 1) {
            if (tid < off) {
                red[tid]       += red[tid + off];
                red[128 + tid] += red[128 + tid + off];
                red[256 + tid] += red[256 + tid + off];
            }
            __syncthreads();
        }
        if (tid == 0) {
            double mean_log = red[0] / (double)NW;
            double mean_sp  = red[128] / (double)NW;
            double kl = -0.5 * ((double)SZ * mean_log - red[256]
                                - (double)SZ * mean_sp);
            out[(size_t)2 * SZ * SZ] = (float)kl;
        }
        __syncthreads();   // scratch free before pipeline overwrites it
    }

    const int wid = tid >> 5;
    const int lid = tid & 31;
    const int lr  = lid >> 2;     // 0..7
    const int lc  = lid & 3;      // 0..3
    const int wm  = wid & 1;      // 0..1 (64 rows)
    const int wn  = wid >> 1;     // 0..1 (32 cols)
    const int m0 = blockIdx.y * BM;
    const int n0 = blockIdx.x * BN;

    const int lrow = lid & 7;
    const int lmat = lid >> 3;

    // Swizzled fragment addressing: addr = rowbase + ((cb + kbytes) ^ xr)
    uint32_t rbA[4], xrA[4];
#pragma unroll
    for (int mt = 0; mt < 4; mt++) {
        uint32_t r = (uint32_t)(wm * 64 + mt * 16 + (lmat & 1) * 8 + lrow);
        rbA[mt] = r * 128u;
        xrA[mt] = (r * 16u) & 0x70u;
    }
    const uint32_t cbA = (uint32_t)((lmat >> 1) * 16);
    uint32_t rbW[2], xrW[2];
#pragma unroll
    for (int ntp = 0; ntp < 2; ntp++) {
        uint32_t r = (uint32_t)(wn * 32 + ntp * 16 + (lmat >> 1) * 8 + lrow);
        rbW[ntp] = r * 128u;
        xrW[ntp] = (r * 16u) & 0x70u;
    }
    const uint32_t cbW = (uint32_t)((lmat & 1) * 16);
    uint32_t rbA2[4], xrA2[4];
#pragma unroll
    for (int mt = 0; mt < 4; mt++) {
        uint32_t r = (uint32_t)(wm * 64 + mt * 16 + (lmat & 1) * 8 + lrow);
        rbA2[mt] = r * 64u;
        xrA2[mt] = (r * 8u) & 0x30u;
    }
    const uint32_t cbA2 = (uint32_t)((lmat >> 1) * 16);
    uint32_t rbW2[2], xrW2[2];
#pragma unroll
    for (int ntp = 0; ntp < 2; ntp++) {
        uint32_t r = (uint32_t)(wn * 32 + ntp * 16 + (lmat >> 1) * 8 + lrow);
        rbW2[ntp] = r * 64u;
        xrW2[ntp] = (r * 8u) & 0x30u;
    }
    const uint32_t cbW2 = (uint32_t)((lmat & 1) * 16);

    float acc1[4][4][4];
    float acc2[4][4][4];
#pragma unroll
    for (int mt = 0; mt < 4; mt++)
#pragma unroll
        for (int nt = 0; nt < 4; nt++)
#pragma unroll
            for (int q = 0; q < 4; q++) { acc1[mt][nt][q] = 0.f; acc2[mt][nt][q] = 0.f; }

    // Stage loader: 18 x 16B cp.async per thread (128 threads)
    auto load_stage = [&](int chunk, int s) {
        const int k0 = chunk * BK;
        const uint32_t base = sb + (uint32_t)s * STAGE_BYTES;
#pragma unroll
        for (int i = 0; i < 8; i++) {           // A tf32: 128 rows x 8 c16
            int f = tid + i * 128;
            int r = f >> 3, cc = f & 7;
            cp16(base + OFF_A + swz128((uint32_t)(r * 128 + cc * 16)),
                 g_a + (size_t)(m0 + r) * SZ + k0 + cc * 4);
        }
#pragma unroll
        for (int i = 0; i < 4; i++) {           // W1 tf32: 64 rows x 8 c16
            int f = tid + i * 128;
            int r = f >> 3, cc = f & 7;
            cp16(base + OFF_W1 + swz128((uint32_t)(r * 128 + cc * 16)),
                 g_w1t + (size_t)(n0 + r) * SZ + k0 + cc * 4);
        }
#pragma unroll
        for (int i = 0; i < 4; i++) {           // A2h bf16: 128 rows x 4 u16
            int f = tid + i * 128;
            int r = f >> 2, u = f & 3;
            cp16(base + OFF_A2 + swz64((uint32_t)(r * 64 + u * 16)),
                 (const char*)g_a2h + ((size_t)(m0 + r) * SZ + k0) * 2 + u * 16);
        }
#pragma unroll
        for (int i = 0; i < 2; i++) {           // W2h bf16: 64 rows x 4 u16
            int f = tid + i * 128;
            int r = f >> 2, u = f & 3;
            cp16(base + OFF_W2 + swz64((uint32_t)(r * 64 + u * 16)),
                 (const char*)g_w2h + ((size_t)(n0 + r) * SZ + k0) * 2 + u * 16);
        }
        asm volatile("cp.async.commit_group;" ::: "memory");
    };

    // mu k-step (kb = k-offset in bytes within stage)
    auto mu_step = [&](uint32_t stA_, uint32_t stW1_, uint32_t kb) {
        uint32_t af[4][4];
#pragma unroll
        for (int mt = 0; mt < 4; mt++)
            LDSM4(af[mt][0], af[mt][1], af[mt][2], af[mt][3],
                  stA_ + rbA[mt] + ((cbA + kb) ^ xrA[mt]));
#pragma unroll
        for (int ntp = 0; ntp < 2; ntp++) {
            uint32_t wf[4];
            LDSM4(wf[0], wf[1], wf[2], wf[3],
                  stW1_ + rbW[ntp] + ((cbW + kb) ^ xrW[ntp]));
#pragma unroll
            for (int h = 0; h < 2; h++) {
                const int nt = ntp * 2 + h;
#pragma unroll
                for (int mt = 0; mt < 4; mt++)
                    MMA_TF32U(acc1[mt][nt], af[mt][0], af[mt][1],
                              af[mt][2], af[mt][3], wf[h * 2], wf[h * 2 + 1]);
            }
        }
    };
    auto sigma_step = [&](uint32_t stA2_, uint32_t stW2_, uint32_t kb) {
        uint32_t a2f[4][4];
#pragma unroll
        for (int mt = 0; mt < 4; mt++)
            LDSM4(a2f[mt][0], a2f[mt][1], a2f[mt][2], a2f[mt][3],
                  stA2_ + rbA2[mt] + ((cbA2 + kb) ^ xrA2[mt]));
#pragma unroll
        for (int ntp = 0; ntp < 2; ntp++) {
            uint32_t wf[4];
            LDSM4(wf[0], wf[1], wf[2], wf[3],
                  stW2_ + rbW2[ntp] + ((cbW2 + kb) ^ xrW2[ntp]));
#pragma unroll
            for (int nb = 0; nb < 2; nb++) {
                const int nt = ntp * 2 + nb;
#pragma unroll
                for (int mt = 0; mt < 4; mt++)
                    MMA_BF16(acc2[mt][nt], a2f[mt][0], a2f[mt][1],
                             a2f[mt][2], a2f[mt][3],
                             wf[nb * 2], wf[nb * 2 + 1]);
            }
        }
    };

    load_stage(0, 0);
    load_stage(1, 1);

    for (int c = 0; c < NCHUNK; c++) {
        const int s = c % 3;
        asm volatile("cp.async.wait_group 1;" ::: "memory");
        __syncthreads();

        const uint32_t stA  = sb + (uint32_t)s * STAGE_BYTES + OFF_A;
        const uint32_t stW1 = sb + (uint32_t)s * STAGE_BYTES + OFF_W1;
        const uint32_t stA2 = sb + (uint32_t)s * STAGE_BYTES + OFF_A2;
        const uint32_t stW2 = sb + (uint32_t)s * STAGE_BYTES + OFF_W2;

        // Start computing immediately after the barrier (mu k-step 0),
        // THEN issue the next-stage prefetch burst (2-chunk slack).
        mu_step(stA, stW1, 0u);

        if (c + 2 < NCHUNK) load_stage(c + 2, (c + 2) % 3);
        else asm volatile("cp.async.commit_group;" ::: "memory");

        mu_step(stA, stW1, 32u);
        sigma_step(stA2, stW2, 0u);
        mu_step(stA, stW1, 64u);
        mu_step(stA, stW1, 96u);
        sigma_step(stA2, stW2, 32u);
    }

    // ---------------- epilogue ----------------
    float* o1 = out;
    float* o2 = out + (size_t)SZ * SZ;
#pragma unroll
    for (int nt = 0; nt < 4; nt++) {
        int col = n0 + wn * 32 + nt * 8 + lc * 2;
        float bm0 = b_mu[col],  bm1 = b_mu[col + 1];
        float bs0 = softplusf(b_sigma[col]), bs1 = softplusf(b_sigma[col + 1]);
#pragma unroll
        for (int mt = 0; mt < 4; mt++) {
            int row = m0 + wm * 64 + mt * 16 + lr;
            float2 v;
            v.x = acc1[mt][nt][0] + bm0; v.y = acc1[mt][nt][1] + bm1;
            *(float2*)(o1 + (size_t)row * SZ + col) = v;
            v.x = acc1[mt][nt][2] + bm0; v.y = acc1[mt][nt][3] + bm1;
            *(float2*)(o1 + (size_t)(row + 8) * SZ + col) = v;
            v.x = acc2[mt][nt][0] + bs0; v.y = acc2[mt][nt][1] + bs1;
            *(float2*)(o2 + (size_t)row * SZ + col) = v;
            v.x = acc2[mt][nt][2] + bs0; v.y = acc2[mt][nt][3] + bs1;
            *(float2*)(o2 + (size_t)(row + 8) * SZ + col) = v;
        }
    }
}

// ---------------- launch -----------------------------------------------------
extern "C" void kernel_launch(void* const* d_in, const int* in_sizes, int n_in,
                              void* d_out, int out_size) {
    const float* mu_in   = (const float*)d_in[0];
    // d_in[1] = sigma_in : unused by the reference outputs
    const float* w_mu    = (const float*)d_in[2];
    const float* w_sigma = (const float*)d_in[3];
    const float* b_mu    = (const float*)d_in[4];
    const float* b_sigma = (const float*)d_in[5];
    float* out = (float*)d_out;

    cudaFuncSetAttribute(gemm_dual, cudaFuncAttributeMaxDynamicSharedMemorySize,
                         SMEM_TOTAL);

    prep_all<<<PREP_W_BLOCKS + 4096, 256>>>(w_mu, w_sigma, mu_in);
    gemm_dual<<<dim3(SZ / BN, SZ / BM), 128, SMEM_TOTAL>>>(b_mu, b_sigma, out);
}